// round 15
// baseline (speedup 1.0000x reference)
#include <cuda_runtime.h>
#include <cuda_fp16.h>
#include <stdint.h>
#include <math.h>

#define D    128
#define TM   32
#define NMAX 50000
#define EMAX 500000
#define NB_MEAN 200

// ---- scratch (device globals: allocation-free) ----
__device__ float  g_h1[NMAX * D];      // h after step 1
__device__ __align__(16) float g_z[NMAX * D];   // aggregation: sum att*relu(u)
__device__ float  g_satt[NMAX];        // aggregation: sum att
__device__ __align__(16) __half g_srcp[NMAX * 256];  // (Pt,At) interleaved half2 pairs
__device__ __align__(16) __half g_dstp[NMAX * 256];  // (Pb,Ab) interleaved half2 pairs
__device__ float  g_Ht[NMAX * D];      // h @ updW1_top
__device__ float  g_M[D * D];          // msgW2 @ updW1_bot (fused, fp32)
__device__ float  g_bb[D];             // msgB2 @ updW1_bot
__device__ float  g_part[NB_MEAN * D];
__device__ float  g_repr[D];
// fp16 weights, MMA-B pair-packed: uint2{b0,b1} at ((WI*128+nrow)*8+kc)*4+t
__device__ __align__(16) uint2 g_WT[7 * D * 32];
// counting sort by dst (CSR)
__device__ int g_cnt[NMAX];
__device__ int g_off[NMAX];
__device__ int g_pos[NMAX];
__device__ int g_es[EMAX];

__device__ __forceinline__ void mma16816(float* d, const unsigned* a,
                                         unsigned b0, unsigned b1) {
    asm volatile(
        "mma.sync.aligned.m16n8k16.row.col.f32.f16.f16.f32 "
        "{%0,%1,%2,%3}, {%4,%5,%6,%7}, {%8,%9}, {%0,%1,%2,%3};"
        : "+f"(d[0]), "+f"(d[1]), "+f"(d[2]), "+f"(d[3])
        : "r"(a[0]), "r"(a[1]), "r"(a[2]), "r"(a[3]), "r"(b0), "r"(b1));
}

__device__ __forceinline__ void ldsm_x4(unsigned* r, unsigned addr) {
    asm volatile("ldmatrix.sync.aligned.m8n8.x4.shared.b16 {%0,%1,%2,%3}, [%4];"
                 : "=r"(r[0]), "=r"(r[1]), "=r"(r[2]), "=r"(r[3]) : "r"(addr));
}

// ---------------- counting sort by dst ----------------
__global__ void hist_kernel(const int* __restrict__ dst, int E, int n) {
    for (int e = blockIdx.x * blockDim.x + threadIdx.x; e < E;
         e += gridDim.x * blockDim.x) {
        int d = dst[e];
        if (d < 0) d = 0; if (d >= n) d = n - 1;
        atomicAdd(&g_cnt[d], 1);
    }
}

// single block, 1024 threads: exclusive prefix sum of g_cnt -> g_off
__global__ void scan_kernel(int n) {
    __shared__ int sh[1024];
    int tid = threadIdx.x;
    int per = (n + 1023) / 1024;
    int i0 = tid * per;
    int s = 0;
    for (int k = 0; k < per; k++) {
        int i = i0 + k;
        if (i < n) s += g_cnt[i];
    }
    sh[tid] = s;
    __syncthreads();
    for (int off = 1; off < 1024; off <<= 1) {
        int v = (tid >= off) ? sh[tid - off] : 0;
        __syncthreads();
        sh[tid] += v;
        __syncthreads();
    }
    int run = (tid > 0) ? sh[tid - 1] : 0;   // exclusive base
    for (int k = 0; k < per; k++) {
        int i = i0 + k;
        if (i < n) { g_off[i] = run; run += g_cnt[i]; }
    }
}

__global__ void scat_kernel(const int* __restrict__ src,
                            const int* __restrict__ dst, int E, int n) {
    for (int e = blockIdx.x * blockDim.x + threadIdx.x; e < E;
         e += gridDim.x * blockDim.x) {
        int d = dst[e], s = src[e];
        if (d < 0) d = 0; if (d >= n) d = n - 1;
        if (s < 0) s = 0; if (s >= n) s = n - 1;
        int p = atomicAdd(&g_pos[d], 1);
        g_es[p] = s;
    }
}

// ---------------- small setup kernels ----------------
__global__ void mean1_kernel(const float* __restrict__ x, int n) {
    int b = blockIdx.x, j = threadIdx.x;
    int per = (n + NB_MEAN - 1) / NB_MEAN;
    int r0 = b * per;
    int r1 = r0 + per; if (r1 > n) r1 = n;
    float s = 0.f;
    for (int r = r0; r < r1; r++) s += x[(size_t)r * D + j];
    g_part[b * D + j] = s;
}

__global__ void repr_kernel(const float* __restrict__ glbW,
                            const float* __restrict__ glbB, int n) {
    __shared__ float meanS[D];
    int j = threadIdx.x;
    float s = 0.f;
    for (int b = 0; b < NB_MEAN; b++) s += g_part[b * D + j];
    meanS[j] = s / (float)n;
    __syncthreads();
    float a = glbB[j];
    #pragma unroll 4
    for (int k = 0; k < D; k++) a = fmaf(meanS[k], glbW[k * D + j], a);
    g_repr[j] = fmaxf(a, 0.f);
}

__global__ void fuse_kernel(const float* __restrict__ msgW2,
                            const float* __restrict__ msgB2,
                            const float* __restrict__ updW1) {
    int k = blockIdx.x, j = threadIdx.x;
    float s = 0.f;
    for (int t = 0; t < D; t++)
        s = fmaf(msgW2[k * D + t], updW1[(D + t) * D + j], s);
    g_M[k * D + j] = s;
    if (k == 0) {
        float b = 0.f;
        for (int t = 0; t < D; t++)
            b = fmaf(msgB2[t], updW1[(D + t) * D + j], b);
        g_bb[j] = b;
    }
}

// convert 7 weight matrices into MMA-B pair-packed fp16 layout (after fuse_kernel)
__global__ void wconv_kernel(const float* __restrict__ msgW1,
                             const float* __restrict__ attW1,
                             const float* __restrict__ updW1,
                             const float* __restrict__ updW2) {
    int nrow = blockIdx.x;
    int m    = blockIdx.y;
    int kc = threadIdx.x >> 2, t = threadIdx.x & 3;

    const float* W; int roff = 0;
    switch (m) {
        case 0: W = msgW1; break;
        case 1: W = attW1; break;
        case 2: W = msgW1; roff = D; break;
        case 3: W = attW1; roff = D; break;
        case 4: W = updW1; break;
        case 5: W = g_M;   break;
        default: W = updW2; break;
    }
    int k0 = 16 * kc + 2 * t;
    __half2 h0 = __floats2half2_rn(W[(roff + k0    ) * D + nrow], W[(roff + k0 + 1) * D + nrow]);
    __half2 h1 = __floats2half2_rn(W[(roff + k0 + 8) * D + nrow], W[(roff + k0 + 9) * D + nrow]);
    uint2 u; u.x = *(unsigned*)&h0; u.y = *(unsigned*)&h1;
    g_WT[((m * D + nrow) * 8 + kc) * 4 + t] = u;
}

// ---- warp-level fp16 MMA GEMM over a 32x128 tile (SRC fp16 smem, stride 136) ----
#define MMA_GEMM(ACC, WI, SRC) { \
    _Pragma("unroll") for (int mt_ = 0; mt_ < 2; mt_++) \
    _Pragma("unroll") for (int nt_ = 0; nt_ < 4; nt_++) \
    _Pragma("unroll") for (int e_ = 0; e_ < 4; e_++) ACC[mt_][nt_][e_] = 0.f; \
    const uint2* WT_ = g_WT + (WI) * D * 32; \
    unsigned aoff0 = (unsigned)__cvta_generic_to_shared(&SRC[lane & 15][8 * (lane >> 4)]); \
    unsigned aoff1 = (unsigned)__cvta_generic_to_shared(&SRC[16 + (lane & 15)][8 * (lane >> 4)]); \
    _Pragma("unroll") \
    for (int kc = 0; kc < 8; kc++) { \
        unsigned a0[4], a1[4]; \
        ldsm_x4(a0, aoff0 + 32 * kc); \
        ldsm_x4(a1, aoff1 + 32 * kc); \
        _Pragma("unroll") \
        for (int nt = 0; nt < 4; nt++) { \
            int nrow_ = 32 * w + 8 * nt + g; \
            uint2 b = WT_[(nrow_ * 8 + kc) * 4 + t]; \
            mma16816(ACC[0][nt], a0, b.x, b.y); \
            mma16816(ACC[1][nt], a1, b.x, b.y); \
        } \
    } }

// interleaved (P,A) half2-pair store matching aggr-kernel layout
#define STORE_ILV(OUT, ACP, ACA) \
    _Pragma("unroll") for (int mt = 0; mt < 2; mt++) \
    _Pragma("unroll") for (int nt = 0; nt < 4; nt++) { \
        int row = 16*mt + g, col = 32*w + 8*nt + 2*t; \
        int node = n0 + row; \
        if (node < n) { \
            __half2 p = __floats2half2_rn(ACP[mt][nt][0], ACP[mt][nt][1]); \
            __half2 a = __floats2half2_rn(ACA[mt][nt][0], ACA[mt][nt][1]); \
            __half2 o0 = __lows2half2(p, a), o1 = __highs2half2(p, a); \
            uint2 u; u.x = *(unsigned*)&o0; u.y = *(unsigned*)&o1; \
            *(uint2*)(OUT + (size_t)node * 256 + 2*col) = u; \
        } \
        int node2 = n0 + row + 8; \
        if (node2 < n) { \
            __half2 p = __floats2half2_rn(ACP[mt][nt][2], ACP[mt][nt][3]); \
            __half2 a = __floats2half2_rn(ACA[mt][nt][2], ACA[mt][nt][3]); \
            __half2 o0 = __lows2half2(p, a), o1 = __highs2half2(p, a); \
            uint2 u; u.x = *(unsigned*)&o0; u.y = *(unsigned*)&o1; \
            *(uint2*)(OUT + (size_t)node2 * 256 + 2*col) = u; \
        } \
    }

// 5 pre GEMMs from fp16 tile SRC -> srcp/dstp/Ht
#define PRE_TAIL(SRC) { \
    float accP[2][4][4], accA[2][4][4]; \
    MMA_GEMM(accP, 0, SRC) \
    MMA_GEMM(accA, 1, SRC) \
    STORE_ILV(g_srcp, accP, accA) \
    MMA_GEMM(accP, 2, SRC) \
    MMA_GEMM(accA, 3, SRC) \
    STORE_ILV(g_dstp, accP, accA) \
    MMA_GEMM(accP, 4, SRC) \
    _Pragma("unroll") for (int mt = 0; mt < 2; mt++) \
    _Pragma("unroll") for (int nt = 0; nt < 4; nt++) { \
        int row = 16*mt + g, col = 32*w + 8*nt + 2*t; \
        int node = n0 + row; \
        if (node < n) { \
            float2 v = make_float2(accP[mt][nt][0], accP[mt][nt][1]); \
            *(float2*)&g_Ht[(size_t)node * D + col] = v; \
        } \
        int node2 = n0 + row + 8; \
        if (node2 < n) { \
            float2 v = make_float2(accP[mt][nt][2], accP[mt][nt][3]); \
            *(float2*)&g_Ht[(size_t)node2 * D + col] = v; \
        } \
    } }

// ---------------- pre kernel: 5 GEMMs via tensor cores ----------------
__global__ __launch_bounds__(128, 4)
void pre_kernel(const float* __restrict__ h, int n)
{
    __shared__ __half hsf[TM][136];
    int tid = threadIdx.x, lane = tid & 31, w = tid >> 5;
    int g = lane >> 2, t = lane & 3;
    int n0 = blockIdx.x * TM;

    for (int i = tid; i < TM * 32; i += 128) {
        int m = i >> 5, q = i & 31;
        int node = n0 + m; if (node >= n) node = n - 1;
        float4 v = ((const float4*)(h + (size_t)node * D))[q];
        *(__half2*)&hsf[m][4*q]     = __floats2half2_rn(v.x, v.y);
        *(__half2*)&hsf[m][4*q + 2] = __floats2half2_rn(v.z, v.w);
    }
    __syncthreads();

    PRE_TAIL(hsf)
}

// ---------------- aggregation kernel: CSR, warp per dst node, no atomics ----------
// Warp v: loads dst row once, loops its incoming edges (2-way unrolled src
// gathers), accumulates z/satt in registers, single plain store at the end.
#define AGGR_EDGE(SU) { \
    float2 s0_ = __half22float2(*(__half2*)&SU.x); \
    float2 s1_ = __half22float2(*(__half2*)&SU.y); \
    float2 s2_ = __half22float2(*(__half2*)&SU.z); \
    float2 s3_ = __half22float2(*(__half2*)&SU.w); \
    float4 rr; \
    rr.x = fmaxf(s0_.x + dd0.x + b1.x, 0.f); \
    rr.y = fmaxf(s1_.x + dd1.x + b1.y, 0.f); \
    rr.z = fmaxf(s2_.x + dd2.x + b1.z, 0.f); \
    rr.w = fmaxf(s3_.x + dd3.x + b1.w, 0.f); \
    float pa = fmaf(fmaxf(s0_.y + dd0.y + a1.x, 0.f), aw.x, \
               fmaf(fmaxf(s1_.y + dd1.y + a1.y, 0.f), aw.y, \
               fmaf(fmaxf(s2_.y + dd2.y + a1.z, 0.f), aw.z, \
                    fmaxf(s3_.y + dd3.y + a1.w, 0.f) * aw.w))); \
    _Pragma("unroll") \
    for (int off_ = 16; off_ > 0; off_ >>= 1) \
        pa += __shfl_xor_sync(0xffffffffu, pa, off_); \
    float a_ = 1.f / (1.f + expf(-(pa + ab2))); \
    accv.x = fmaf(rr.x, a_, accv.x); \
    accv.y = fmaf(rr.y, a_, accv.y); \
    accv.z = fmaf(rr.z, a_, accv.z); \
    accv.w = fmaf(rr.w, a_, accv.w); \
    acca += a_; }

__global__ __launch_bounds__(256, 6)
void aggr_kernel(const float* __restrict__ msgB1,
                 const float* __restrict__ attB1,
                 const float* __restrict__ attW2,
                 const float* __restrict__ attB2, int E, int n)
{
    int v    = (blockIdx.x * 256 + threadIdx.x) >> 5;
    int lane = threadIdx.x & 31;
    if (v >= n) return;

    int beg = g_off[v];
    int end = (v + 1 < n) ? g_off[v + 1] : E;

    const uint4* SP = (const uint4*)g_srcp;
    const uint4* DP = (const uint4*)g_dstp;
    uint4 du = DP[(size_t)v * 32 + lane];
    float2 dd0 = __half22float2(*(__half2*)&du.x);
    float2 dd1 = __half22float2(*(__half2*)&du.y);
    float2 dd2 = __half22float2(*(__half2*)&du.z);
    float2 dd3 = __half22float2(*(__half2*)&du.w);
    float4 b1 = *(const float4*)&msgB1[4*lane];
    float4 a1 = *(const float4*)&attB1[4*lane];
    float4 aw = *(const float4*)&attW2[4*lane];
    float ab2 = attB2[0];

    float4 accv = make_float4(0.f, 0.f, 0.f, 0.f);
    float  acca = 0.f;

    int e = beg;
    for (; e + 1 < end; e += 2) {
        int s0 = g_es[e], s1 = g_es[e + 1];
        uint4 su0 = SP[(size_t)s0 * 32 + lane];
        uint4 su1 = SP[(size_t)s1 * 32 + lane];
        AGGR_EDGE(su0)
        AGGR_EDGE(su1)
    }
    if (e < end) {
        int s0 = g_es[e];
        uint4 su0 = SP[(size_t)s0 * 32 + lane];
        AGGR_EDGE(su0)
    }

    *(float4*)&g_z[(size_t)v * D + 4*lane] = accv;
    if (lane == 0) g_satt[v] = acca;
}

// ---- shared update body ----
#define UPD_PHASES() \
    MMA_GEMM(acc, 5, zsf) \
    _Pragma("unroll") for (int mt = 0; mt < 2; mt++) \
    _Pragma("unroll") for (int nt = 0; nt < 4; nt++) { \
        int row = 16*mt + g, col = 32*w + 8*nt + 2*t; \
        float2 bb = *(const float2*)&g_bb[col]; \
        float2 b1v = *(const float2*)&updB1[col]; \
        { \
            int node = n0 + row; \
            int nc = node < n ? node : n - 1; \
            float2 ht = *(const float2*)&g_Ht[(size_t)nc * D + col]; \
            float sa = g_satt[nc]; \
            float v0 = fmaxf(acc[mt][nt][0] + ht.x + sa * bb.x + b1v.x, 0.f); \
            float v1 = fmaxf(acc[mt][nt][1] + ht.y + sa * bb.y + b1v.y, 0.f); \
            *(__half2*)&hid[row][col] = __floats2half2_rn(v0, v1); \
        } \
        { \
            int node = n0 + row + 8; \
            int nc = node < n ? node : n - 1; \
            float2 ht = *(const float2*)&g_Ht[(size_t)nc * D + col]; \
            float sa = g_satt[nc]; \
            float v0 = fmaxf(acc[mt][nt][2] + ht.x + sa * bb.x + b1v.x, 0.f); \
            float v1 = fmaxf(acc[mt][nt][3] + ht.y + sa * bb.y + b1v.y, 0.f); \
            *(__half2*)&hid[row + 8][col] = __floats2half2_rn(v0, v1); \
        } \
    } \
    __syncthreads(); \
    MMA_GEMM(acc, 6, hid)

// ---------------- final update kernel (step 2) ----------------
__global__ __launch_bounds__(128, 4)
void upd_kernel(const float* __restrict__ h,
                const float* __restrict__ updB1,
                const float* __restrict__ updB2,
                float* __restrict__ out, int n)
{
    __shared__ __half zsf[TM][136];
    __shared__ __half hid[TM][136];
    int tid = threadIdx.x, lane = tid & 31, w = tid >> 5;
    int g = lane >> 2, t = lane & 3;
    int n0 = blockIdx.x * TM;

    for (int i = tid; i < TM * 32; i += 128) {
        int m = i >> 5, q = i & 31;
        int node = n0 + m; if (node >= n) node = n - 1;
        float4 v = ((const float4*)(g_z + (size_t)node * D))[q];
        *(__half2*)&zsf[m][4*q]     = __floats2half2_rn(v.x, v.y);
        *(__half2*)&zsf[m][4*q + 2] = __floats2half2_rn(v.z, v.w);
    }
    __syncthreads();

    float acc[2][4][4];
    UPD_PHASES()

    #pragma unroll
    for (int mt = 0; mt < 2; mt++)
    #pragma unroll
    for (int nt = 0; nt < 4; nt++) {
        int row = 16*mt + g, col = 32*w + 8*nt + 2*t;
        float2 b2 = *(const float2*)&updB2[col];
        float2 gr = *(const float2*)&g_repr[col];
        {
            int node = n0 + row;
            if (node < n) {
                float2 hv = *(const float2*)&h[(size_t)node * D + col];
                float2 o = make_float2(acc[mt][nt][0] + b2.x + hv.x + gr.x,
                                       acc[mt][nt][1] + b2.y + hv.y + gr.y);
                *(float2*)&out[(size_t)node * D + col] = o;
            }
        }
        {
            int node = n0 + row + 8;
            if (node < n) {
                float2 hv = *(const float2*)&h[(size_t)node * D + col];
                float2 o = make_float2(acc[mt][nt][2] + b2.x + hv.x + gr.x,
                                       acc[mt][nt][3] + b2.y + hv.y + gr.y);
                *(float2*)&out[(size_t)node * D + col] = o;
            }
        }
    }
}

// ---------------- fused: step-1 update + step-2 pre (same node tile) ----------------
__global__ __launch_bounds__(128, 3)
void updpre_kernel(const float* __restrict__ h,
                   const float* __restrict__ updB1,
                   const float* __restrict__ updB2,
                   float* __restrict__ h1out, int n)
{
    __shared__ __half zsf[TM][136];
    __shared__ __half hid[TM][136];
    int tid = threadIdx.x, lane = tid & 31, w = tid >> 5;
    int g = lane >> 2, t = lane & 3;
    int n0 = blockIdx.x * TM;

    for (int i = tid; i < TM * 32; i += 128) {
        int m = i >> 5, q = i & 31;
        int node = n0 + m; if (node >= n) node = n - 1;
        float4 v = ((const float4*)(g_z + (size_t)node * D))[q];
        *(__half2*)&zsf[m][4*q]     = __floats2half2_rn(v.x, v.y);
        *(__half2*)&zsf[m][4*q + 2] = __floats2half2_rn(v.z, v.w);
    }
    __syncthreads();

    {
        float acc[2][4][4];
        UPD_PHASES()

        // epilogue: h1 = acc + b2 + h + repr -> store fp32 AND pack fp16 into zsf
        #pragma unroll
        for (int mt = 0; mt < 2; mt++)
        #pragma unroll
        for (int nt = 0; nt < 4; nt++) {
            int row = 16*mt + g, col = 32*w + 8*nt + 2*t;
            float2 b2 = *(const float2*)&updB2[col];
            float2 gr = *(const float2*)&g_repr[col];
            {
                int node = n0 + row;
                int nc = node < n ? node : n - 1;
                float2 hv = *(const float2*)&h[(size_t)nc * D + col];
                float2 o = make_float2(acc[mt][nt][0] + b2.x + hv.x + gr.x,
                                       acc[mt][nt][1] + b2.y + hv.y + gr.y);
                if (node < n) *(float2*)&h1out[(size_t)node * D + col] = o;
                *(__half2*)&zsf[row][col] = __floats2half2_rn(o.x, o.y);
            }
            {
                int node = n0 + row + 8;
                int nc = node < n ? node : n - 1;
                float2 hv = *(const float2*)&h[(size_t)nc * D + col];
                float2 o = make_float2(acc[mt][nt][2] + b2.x + hv.x + gr.x,
                                       acc[mt][nt][3] + b2.y + hv.y + gr.y);
                if (node < n) *(float2*)&h1out[(size_t)node * D + col] = o;
                *(__half2*)&zsf[row + 8][col] = __floats2half2_rn(o.x, o.y);
            }
        }
    }
    __syncthreads();

    // step-2 pre: 5 GEMMs on the h1 tile already in zsf
    PRE_TAIL(zsf)
}

// ---------------- launch ----------------
extern "C" void kernel_launch(void* const* d_in, const int* in_sizes, int n_in,
                              void* d_out, int out_size)
{
    const float* x  = (const float*)d_in[0];
    const int*   ei = (const int*)d_in[1];     // int32 (JAX x64 disabled)
    const float* msgW1 = (const float*)d_in[2];
    const float* msgB1 = (const float*)d_in[3];
    const float* msgW2 = (const float*)d_in[4];
    const float* msgB2 = (const float*)d_in[5];
    const float* updW1 = (const float*)d_in[6];
    const float* updB1 = (const float*)d_in[7];
    const float* updW2 = (const float*)d_in[8];
    const float* updB2 = (const float*)d_in[9];
    const float* attW1 = (const float*)d_in[10];
    const float* attB1 = (const float*)d_in[11];
    const float* attW2 = (const float*)d_in[12];
    const float* attB2 = (const float*)d_in[13];
    const float* glbW  = (const float*)d_in[14];
    const float* glbB  = (const float*)d_in[15];

    int n = in_sizes[0] / D;
    int E = in_sizes[1] / 2;
    const int* src  = ei;
    const int* dstp = ei + E;
    float* out = (float*)d_out;

    float* h1 = nullptr;
    int *cntP = nullptr, *offP = nullptr, *posP = nullptr;
    cudaGetSymbolAddress((void**)&h1,   g_h1);
    cudaGetSymbolAddress((void**)&cntP, g_cnt);
    cudaGetSymbolAddress((void**)&offP, g_off);
    cudaGetSymbolAddress((void**)&posP, g_pos);

    int nb = (n + TM - 1) / TM;
    int gb = (E + 1023) / 1024;
    int ab = (n * 32 + 255) / 256;   // aggr: warp per node

    // fixed across steps
    mean1_kernel<<<NB_MEAN, 128>>>(x, n);
    repr_kernel<<<1, 128>>>(glbW, glbB, n);
    fuse_kernel<<<D, 128>>>(msgW2, msgB2, updW1);
    wconv_kernel<<<dim3(D, 7), 32>>>(msgW1, attW1, updW1, updW2);

    // CSR by dst (counting sort; deterministic work every call)
    cudaMemsetAsync(cntP, 0, (size_t)n * sizeof(int));
    hist_kernel<<<gb, 1024>>>(dstp, E, n);
    scan_kernel<<<1, 1024>>>(n);
    cudaMemcpyAsync(posP, offP, (size_t)n * sizeof(int), cudaMemcpyDeviceToDevice);
    scat_kernel<<<gb, 1024>>>(src, dstp, E, n);

    // step 1: h = x
    pre_kernel<<<nb, 128>>>(x, n);
    aggr_kernel<<<ab, 256>>>(msgB1, attB1, attW2, attB2, E, n);
    updpre_kernel<<<nb, 128>>>(x, updB1, updB2, h1, n);   // upd(step1) + pre(step2)

    // step 2
    aggr_kernel<<<ab, 256>>>(msgB1, attB1, attW2, attB2, E, n);
    upd_kernel<<<nb, 128>>>(h1, updB1, updB2, out, n);
}

// round 16
// speedup vs baseline: 1.0974x; 1.0974x over previous
#include <cuda_runtime.h>
#include <cuda_fp16.h>
#include <stdint.h>
#include <math.h>

#define D   128
#define TM  32
#define NMAX 50000
#define NB_MEAN 200

// ---- scratch (device globals: allocation-free) ----
__device__ float  g_h1[NMAX * D];      // h after step 1
__device__ __align__(16) float g_z[NMAX * D];   // scatter: sum att*relu(u)
__device__ float  g_satt[NMAX];        // scatter: sum att
__device__ __align__(16) __half g_srcp[NMAX * 256];  // (Pt,At) interleaved half2 pairs
__device__ __align__(16) __half g_dstp[NMAX * 256];  // (Pb,Ab) interleaved half2 pairs
__device__ float  g_Ht[NMAX * D];      // h @ updW1_top
__device__ float  g_M[D * D];          // msgW2 @ updW1_bot (fused, fp32)
__device__ float  g_bb[D];             // msgB2 @ updW1_bot
__device__ float  g_part[NB_MEAN * D];
__device__ float  g_repr[D];
// fp16 weights, MMA-B pair-packed: uint2{b0,b1} at ((WI*128+nrow)*8+kc)*4+t
// WI: 0:msgW1top 1:attW1top 2:msgW1bot 3:attW1bot 4:updW1top 5:M 6:updW2
__device__ __align__(16) uint2 g_WT[7 * D * 32];

__device__ __forceinline__ void red_add_v4(float* a, float4 v) {
    asm volatile("red.global.add.v4.f32 [%0], {%1,%2,%3,%4};"
                 :: "l"(a), "f"(v.x), "f"(v.y), "f"(v.z), "f"(v.w) : "memory");
}

__device__ __forceinline__ void mma16816(float* d, const unsigned* a,
                                         unsigned b0, unsigned b1) {
    asm volatile(
        "mma.sync.aligned.m16n8k16.row.col.f32.f16.f16.f32 "
        "{%0,%1,%2,%3}, {%4,%5,%6,%7}, {%8,%9}, {%0,%1,%2,%3};"
        : "+f"(d[0]), "+f"(d[1]), "+f"(d[2]), "+f"(d[3])
        : "r"(a[0]), "r"(a[1]), "r"(a[2]), "r"(a[3]), "r"(b0), "r"(b1));
}

__device__ __forceinline__ void ldsm_x4(unsigned* r, unsigned addr) {
    asm volatile("ldmatrix.sync.aligned.m8n8.x4.shared.b16 {%0,%1,%2,%3}, [%4];"
                 : "=r"(r[0]), "=r"(r[1]), "=r"(r[2]), "=r"(r[3]) : "r"(addr));
}

// ---------------- small setup kernels ----------------
__global__ void mean1_kernel(const float* __restrict__ x, int n) {
    int b = blockIdx.x, j = threadIdx.x;
    int per = (n + NB_MEAN - 1) / NB_MEAN;
    int r0 = b * per;
    int r1 = r0 + per; if (r1 > n) r1 = n;
    float s = 0.f;
    for (int r = r0; r < r1; r++) s += x[(size_t)r * D + j];
    g_part[b * D + j] = s;
}

__global__ void repr_kernel(const float* __restrict__ glbW,
                            const float* __restrict__ glbB, int n) {
    __shared__ float meanS[D];
    int j = threadIdx.x;
    float s = 0.f;
    for (int b = 0; b < NB_MEAN; b++) s += g_part[b * D + j];
    meanS[j] = s / (float)n;
    __syncthreads();
    float a = glbB[j];
    #pragma unroll 4
    for (int k = 0; k < D; k++) a = fmaf(meanS[k], glbW[k * D + j], a);
    g_repr[j] = fmaxf(a, 0.f);
}

__global__ void fuse_kernel(const float* __restrict__ msgW2,
                            const float* __restrict__ msgB2,
                            const float* __restrict__ updW1) {
    int k = blockIdx.x, j = threadIdx.x;
    float s = 0.f;
    for (int t = 0; t < D; t++)
        s = fmaf(msgW2[k * D + t], updW1[(D + t) * D + j], s);
    g_M[k * D + j] = s;
    if (k == 0) {
        float b = 0.f;
        for (int t = 0; t < D; t++)
            b = fmaf(msgB2[t], updW1[(D + t) * D + j], b);
        g_bb[j] = b;
    }
}

// convert 7 weight matrices into MMA-B pair-packed fp16 layout (after fuse_kernel)
__global__ void wconv_kernel(const float* __restrict__ msgW1,
                             const float* __restrict__ attW1,
                             const float* __restrict__ updW1,
                             const float* __restrict__ updW2) {
    int nrow = blockIdx.x;
    int m    = blockIdx.y;
    int kc = threadIdx.x >> 2, t = threadIdx.x & 3;

    const float* W; int roff = 0;
    switch (m) {
        case 0: W = msgW1; break;
        case 1: W = attW1; break;
        case 2: W = msgW1; roff = D; break;
        case 3: W = attW1; roff = D; break;
        case 4: W = updW1; break;
        case 5: W = g_M;   break;
        default: W = updW2; break;
    }
    int k0 = 16 * kc + 2 * t;
    __half2 h0 = __floats2half2_rn(W[(roff + k0    ) * D + nrow], W[(roff + k0 + 1) * D + nrow]);
    __half2 h1 = __floats2half2_rn(W[(roff + k0 + 8) * D + nrow], W[(roff + k0 + 9) * D + nrow]);
    uint2 u; u.x = *(unsigned*)&h0; u.y = *(unsigned*)&h1;
    g_WT[((m * D + nrow) * 8 + kc) * 4 + t] = u;
}

// ---- warp-level fp16 MMA GEMM over a 32x128 tile (SRC fp16 smem, stride 136) ----
#define MMA_GEMM(ACC, WI, SRC) { \
    _Pragma("unroll") for (int mt_ = 0; mt_ < 2; mt_++) \
    _Pragma("unroll") for (int nt_ = 0; nt_ < 4; nt_++) \
    _Pragma("unroll") for (int e_ = 0; e_ < 4; e_++) ACC[mt_][nt_][e_] = 0.f; \
    const uint2* WT_ = g_WT + (WI) * D * 32; \
    unsigned aoff0 = (unsigned)__cvta_generic_to_shared(&SRC[lane & 15][8 * (lane >> 4)]); \
    unsigned aoff1 = (unsigned)__cvta_generic_to_shared(&SRC[16 + (lane & 15)][8 * (lane >> 4)]); \
    _Pragma("unroll") \
    for (int kc = 0; kc < 8; kc++) { \
        unsigned a0[4], a1[4]; \
        ldsm_x4(a0, aoff0 + 32 * kc); \
        ldsm_x4(a1, aoff1 + 32 * kc); \
        _Pragma("unroll") \
        for (int nt = 0; nt < 4; nt++) { \
            int nrow_ = 32 * w + 8 * nt + g; \
            uint2 b = WT_[(nrow_ * 8 + kc) * 4 + t]; \
            mma16816(ACC[0][nt], a0, b.x, b.y); \
            mma16816(ACC[1][nt], a1, b.x, b.y); \
        } \
    } }

// interleaved (P,A) half2-pair store matching edge-kernel layout
#define STORE_ILV(OUT, ACP, ACA) \
    _Pragma("unroll") for (int mt = 0; mt < 2; mt++) \
    _Pragma("unroll") for (int nt = 0; nt < 4; nt++) { \
        int row = 16*mt + g, col = 32*w + 8*nt + 2*t; \
        int node = n0 + row; \
        if (node < n) { \
            __half2 p = __floats2half2_rn(ACP[mt][nt][0], ACP[mt][nt][1]); \
            __half2 a = __floats2half2_rn(ACA[mt][nt][0], ACA[mt][nt][1]); \
            __half2 o0 = __lows2half2(p, a), o1 = __highs2half2(p, a); \
            uint2 u; u.x = *(unsigned*)&o0; u.y = *(unsigned*)&o1; \
            *(uint2*)(OUT + (size_t)node * 256 + 2*col) = u; \
        } \
        int node2 = n0 + row + 8; \
        if (node2 < n) { \
            __half2 p = __floats2half2_rn(ACP[mt][nt][2], ACP[mt][nt][3]); \
            __half2 a = __floats2half2_rn(ACA[mt][nt][2], ACA[mt][nt][3]); \
            __half2 o0 = __lows2half2(p, a), o1 = __highs2half2(p, a); \
            uint2 u; u.x = *(unsigned*)&o0; u.y = *(unsigned*)&o1; \
            *(uint2*)(OUT + (size_t)node2 * 256 + 2*col) = u; \
        } \
    }

// 5 pre GEMMs from fp16 tile SRC -> srcp/dstp/Ht
#define PRE_TAIL(SRC) { \
    float accP[2][4][4], accA[2][4][4]; \
    MMA_GEMM(accP, 0, SRC) \
    MMA_GEMM(accA, 1, SRC) \
    STORE_ILV(g_srcp, accP, accA) \
    MMA_GEMM(accP, 2, SRC) \
    MMA_GEMM(accA, 3, SRC) \
    STORE_ILV(g_dstp, accP, accA) \
    MMA_GEMM(accP, 4, SRC) \
    _Pragma("unroll") for (int mt = 0; mt < 2; mt++) \
    _Pragma("unroll") for (int nt = 0; nt < 4; nt++) { \
        int row = 16*mt + g, col = 32*w + 8*nt + 2*t; \
        int node = n0 + row; \
        if (node < n) { \
            float2 v = make_float2(accP[mt][nt][0], accP[mt][nt][1]); \
            *(float2*)&g_Ht[(size_t)node * D + col] = v; \
        } \
        int node2 = n0 + row + 8; \
        if (node2 < n) { \
            float2 v = make_float2(accP[mt][nt][2], accP[mt][nt][3]); \
            *(float2*)&g_Ht[(size_t)node2 * D + col] = v; \
        } \
    } }

// ---------------- pre kernel: 5 GEMMs via tensor cores ----------------
__global__ __launch_bounds__(128, 4)
void pre_kernel(const float* __restrict__ h, int n)
{
    __shared__ __half hsf[TM][136];
    int tid = threadIdx.x, lane = tid & 31, w = tid >> 5;
    int g = lane >> 2, t = lane & 3;
    int n0 = blockIdx.x * TM;

    for (int i = tid; i < TM * 32; i += 128) {
        int m = i >> 5, q = i & 31;
        int node = n0 + m; if (node >= n) node = n - 1;
        float4 v = ((const float4*)(h + (size_t)node * D))[q];
        *(__half2*)&hsf[m][4*q]     = __floats2half2_rn(v.x, v.y);
        *(__half2*)&hsf[m][4*q + 2] = __floats2half2_rn(v.z, v.w);
    }
    __syncthreads();

    PRE_TAIL(hsf)
}

// ---------------- edge kernel: warp-autonomous, zero smem (R11/R13 form) ------------
__global__ __launch_bounds__(128, 8)
void edge_kernel(const int* __restrict__ src, const int* __restrict__ dst,
                 const float* __restrict__ msgB1,
                 const float* __restrict__ attB1,
                 const float* __restrict__ attW2,
                 const float* __restrict__ attB2, int E, int n)
{
    int j    = threadIdx.x;
    int lane = j & 31, mg = j >> 5;
    int e0   = blockIdx.x * TM + mg * 8;
    int q    = lane;

    int eL = e0 + (lane & 7);
    int sL = 0, dL = 0;
    if (eL < E) { sL = src[eL]; dL = dst[eL]; }
    if (sL < 0) sL = 0; if (sL >= n) sL = n - 1;
    if (dL < 0) dL = 0; if (dL >= n) dL = n - 1;

    const uint4* SP = (const uint4*)g_srcp;
    const uint4* DP = (const uint4*)g_dstp;
    float4 b1 = *(const float4*)&msgB1[4*q];
    float4 a1 = *(const float4*)&attB1[4*q];
    float4 aw = *(const float4*)&attW2[4*q];
    float ab2 = attB2[0];

    int sA[8], dA[8];
    #pragma unroll
    for (int r8 = 0; r8 < 8; r8++) {
        sA[r8] = __shfl_sync(0xffffffffu, sL, r8);
        dA[r8] = __shfl_sync(0xffffffffu, dL, r8);
    }

    #pragma unroll
    for (int r8 = 0; r8 < 8; r8++) {
        uint4 su = SP[(size_t)sA[r8] * 32 + q];
        uint4 du = DP[(size_t)dA[r8] * 32 + q];
        float2 s0 = __half22float2(*(__half2*)&su.x), d0 = __half22float2(*(__half2*)&du.x);
        float2 s1 = __half22float2(*(__half2*)&su.y), d1 = __half22float2(*(__half2*)&du.y);
        float2 s2 = __half22float2(*(__half2*)&su.z), d2 = __half22float2(*(__half2*)&du.z);
        float2 s3 = __half22float2(*(__half2*)&su.w), d3 = __half22float2(*(__half2*)&du.w);

        float4 rr;
        rr.x = fmaxf(s0.x + d0.x + b1.x, 0.f);
        rr.y = fmaxf(s1.x + d1.x + b1.y, 0.f);
        rr.z = fmaxf(s2.x + d2.x + b1.z, 0.f);
        rr.w = fmaxf(s3.x + d3.x + b1.w, 0.f);

        float pa = fmaf(fmaxf(s0.y + d0.y + a1.x, 0.f), aw.x,
                   fmaf(fmaxf(s1.y + d1.y + a1.y, 0.f), aw.y,
                   fmaf(fmaxf(s2.y + d2.y + a1.z, 0.f), aw.z,
                        fmaxf(s3.y + d3.y + a1.w, 0.f) * aw.w)));
        #pragma unroll
        for (int off = 16; off > 0; off >>= 1)
            pa += __shfl_xor_sync(0xffffffffu, pa, off);

        // fast sigmoid: approx exp + approx divide (err ~1e-6, << 1e-3 gate)
        float a = __fdividef(1.f, 1.f + __expf(-(pa + ab2)));

        if (e0 + r8 < E) {
            float4 v = make_float4(rr.x * a, rr.y * a, rr.z * a, rr.w * a);
            red_add_v4(&g_z[(size_t)dA[r8] * D + 4*q], v);
            if (lane == 0) atomicAdd(&g_satt[dA[r8]], a);
        }
    }
}

// ---- shared update body ----
#define UPD_PHASES() \
    MMA_GEMM(acc, 5, zsf) \
    _Pragma("unroll") for (int mt = 0; mt < 2; mt++) \
    _Pragma("unroll") for (int nt = 0; nt < 4; nt++) { \
        int row = 16*mt + g, col = 32*w + 8*nt + 2*t; \
        float2 bb = *(const float2*)&g_bb[col]; \
        float2 b1v = *(const float2*)&updB1[col]; \
        { \
            int node = n0 + row; \
            int nc = node < n ? node : n - 1; \
            float2 ht = *(const float2*)&g_Ht[(size_t)nc * D + col]; \
            float sa = g_satt[nc]; \
            float v0 = fmaxf(acc[mt][nt][0] + ht.x + sa * bb.x + b1v.x, 0.f); \
            float v1 = fmaxf(acc[mt][nt][1] + ht.y + sa * bb.y + b1v.y, 0.f); \
            *(__half2*)&hid[row][col] = __floats2half2_rn(v0, v1); \
        } \
        { \
            int node = n0 + row + 8; \
            int nc = node < n ? node : n - 1; \
            float2 ht = *(const float2*)&g_Ht[(size_t)nc * D + col]; \
            float sa = g_satt[nc]; \
            float v0 = fmaxf(acc[mt][nt][2] + ht.x + sa * bb.x + b1v.x, 0.f); \
            float v1 = fmaxf(acc[mt][nt][3] + ht.y + sa * bb.y + b1v.y, 0.f); \
            *(__half2*)&hid[row + 8][col] = __floats2half2_rn(v0, v1); \
        } \
    } \
    __syncthreads(); \
    MMA_GEMM(acc, 6, hid)

// ---------------- final update kernel (step 2) ----------------
__global__ __launch_bounds__(128, 4)
void upd_kernel(const float* __restrict__ h,
                const float* __restrict__ updB1,
                const float* __restrict__ updB2,
                float* __restrict__ out, int n)
{
    __shared__ __half zsf[TM][136];
    __shared__ __half hid[TM][136];
    int tid = threadIdx.x, lane = tid & 31, w = tid >> 5;
    int g = lane >> 2, t = lane & 3;
    int n0 = blockIdx.x * TM;

    for (int i = tid; i < TM * 32; i += 128) {
        int m = i >> 5, q = i & 31;
        int node = n0 + m; if (node >= n) node = n - 1;
        float4 v = ((const float4*)(g_z + (size_t)node * D))[q];
        *(__half2*)&zsf[m][4*q]     = __floats2half2_rn(v.x, v.y);
        *(__half2*)&zsf[m][4*q + 2] = __floats2half2_rn(v.z, v.w);
    }
    __syncthreads();

    float acc[2][4][4];
    UPD_PHASES()

    #pragma unroll
    for (int mt = 0; mt < 2; mt++)
    #pragma unroll
    for (int nt = 0; nt < 4; nt++) {
        int row = 16*mt + g, col = 32*w + 8*nt + 2*t;
        float2 b2 = *(const float2*)&updB2[col];
        float2 gr = *(const float2*)&g_repr[col];
        {
            int node = n0 + row;
            if (node < n) {
                float2 hv = *(const float2*)&h[(size_t)node * D + col];
                float2 o = make_float2(acc[mt][nt][0] + b2.x + hv.x + gr.x,
                                       acc[mt][nt][1] + b2.y + hv.y + gr.y);
                *(float2*)&out[(size_t)node * D + col] = o;
            }
        }
        {
            int node = n0 + row + 8;
            if (node < n) {
                float2 hv = *(const float2*)&h[(size_t)node * D + col];
                float2 o = make_float2(acc[mt][nt][2] + b2.x + hv.x + gr.x,
                                       acc[mt][nt][3] + b2.y + hv.y + gr.y);
                *(float2*)&out[(size_t)node * D + col] = o;
            }
        }
    }
}

// ---------------- fused: step-1 update + step-2 pre (same node tile) ----------------
__global__ __launch_bounds__(128, 3)
void updpre_kernel(const float* __restrict__ h,
                   const float* __restrict__ updB1,
                   const float* __restrict__ updB2,
                   float* __restrict__ h1out, int n)
{
    __shared__ __half zsf[TM][136];
    __shared__ __half hid[TM][136];
    int tid = threadIdx.x, lane = tid & 31, w = tid >> 5;
    int g = lane >> 2, t = lane & 3;
    int n0 = blockIdx.x * TM;

    for (int i = tid; i < TM * 32; i += 128) {
        int m = i >> 5, q = i & 31;
        int node = n0 + m; if (node >= n) node = n - 1;
        float4 v = ((const float4*)(g_z + (size_t)node * D))[q];
        *(__half2*)&zsf[m][4*q]     = __floats2half2_rn(v.x, v.y);
        *(__half2*)&zsf[m][4*q + 2] = __floats2half2_rn(v.z, v.w);
    }
    __syncthreads();

    {
        float acc[2][4][4];
        UPD_PHASES()

        // epilogue: h1 = acc + b2 + h + repr -> store fp32 AND pack fp16 into zsf
        #pragma unroll
        for (int mt = 0; mt < 2; mt++)
        #pragma unroll
        for (int nt = 0; nt < 4; nt++) {
            int row = 16*mt + g, col = 32*w + 8*nt + 2*t;
            float2 b2 = *(const float2*)&updB2[col];
            float2 gr = *(const float2*)&g_repr[col];
            {
                int node = n0 + row;
                int nc = node < n ? node : n - 1;
                float2 hv = *(const float2*)&h[(size_t)nc * D + col];
                float2 o = make_float2(acc[mt][nt][0] + b2.x + hv.x + gr.x,
                                       acc[mt][nt][1] + b2.y + hv.y + gr.y);
                if (node < n) *(float2*)&h1out[(size_t)node * D + col] = o;
                *(__half2*)&zsf[row][col] = __floats2half2_rn(o.x, o.y);
            }
            {
                int node = n0 + row + 8;
                int nc = node < n ? node : n - 1;
                float2 hv = *(const float2*)&h[(size_t)nc * D + col];
                float2 o = make_float2(acc[mt][nt][2] + b2.x + hv.x + gr.x,
                                       acc[mt][nt][3] + b2.y + hv.y + gr.y);
                if (node < n) *(float2*)&h1out[(size_t)node * D + col] = o;
                *(__half2*)&zsf[row + 8][col] = __floats2half2_rn(o.x, o.y);
            }
        }
    }
    __syncthreads();

    // step-2 pre: 5 GEMMs on the h1 tile already in zsf
    PRE_TAIL(zsf)
}

// ---------------- launch ----------------
extern "C" void kernel_launch(void* const* d_in, const int* in_sizes, int n_in,
                              void* d_out, int out_size)
{
    const float* x  = (const float*)d_in[0];
    const int*   ei = (const int*)d_in[1];     // int32 (JAX x64 disabled)
    const float* msgW1 = (const float*)d_in[2];
    const float* msgB1 = (const float*)d_in[3];
    const float* msgW2 = (const float*)d_in[4];
    const float* msgB2 = (const float*)d_in[5];
    const float* updW1 = (const float*)d_in[6];
    const float* updB1 = (const float*)d_in[7];
    const float* updW2 = (const float*)d_in[8];
    const float* updB2 = (const float*)d_in[9];
    const float* attW1 = (const float*)d_in[10];
    const float* attB1 = (const float*)d_in[11];
    const float* attW2 = (const float*)d_in[12];
    const float* attB2 = (const float*)d_in[13];
    const float* glbW  = (const float*)d_in[14];
    const float* glbB  = (const float*)d_in[15];

    int n = in_sizes[0] / D;
    int E = in_sizes[1] / 2;
    const int* src  = ei;
    const int* dstp = ei + E;
    float* out = (float*)d_out;

    float* h1 = nullptr; float* zP = nullptr; float* saP = nullptr;
    cudaGetSymbolAddress((void**)&h1,  g_h1);
    cudaGetSymbolAddress((void**)&zP,  g_z);
    cudaGetSymbolAddress((void**)&saP, g_satt);

    int eb = (E + TM - 1) / TM;
    int nb = (n + TM - 1) / TM;

    // step-1 scatter buffers first (overlaps the serial setup chain below)
    cudaMemsetAsync(zP, 0, (size_t)n * D * sizeof(float));
    cudaMemsetAsync(saP, 0, (size_t)n * sizeof(float));

    // fixed across steps
    mean1_kernel<<<NB_MEAN, 128>>>(x, n);
    repr_kernel<<<1, 128>>>(glbW, glbB, n);
    fuse_kernel<<<D, 128>>>(msgW2, msgB2, updW1);
    wconv_kernel<<<dim3(D, 7), 32>>>(msgW1, attW1, updW1, updW2);

    // step 1: h = x
    pre_kernel<<<nb, 128>>>(x, n);
    edge_kernel<<<eb, 128>>>(src, dstp, msgB1, attB1, attW2, attB2, E, n);
    // fused: upd (step 1) + pre (step 2)
    updpre_kernel<<<nb, 128>>>(x, updB1, updB2, h1, n);

    // step 2
    cudaMemsetAsync(zP, 0, (size_t)n * D * sizeof(float));
    cudaMemsetAsync(saP, 0, (size_t)n * sizeof(float));
    edge_kernel<<<eb, 128>>>(src, dstp, msgB1, attB1, attW2, attB2, E, n);
    upd_kernel<<<nb, 128>>>(h1, updB1, updB2, out, n);
}